// round 4
// baseline (speedup 1.0000x reference)
#include <cuda_runtime.h>
#include <cuda_bf16.h>
#include <cstdint>

// Problem constants
#define BB 8
#define SS 64
#define NN 256
#define FF 16
#define HH 16
#define CC 4096            // N*H  (= GEMM M)
#define COLS 512           // B*S  (= GEMM Ncol)
#define KTOT 12288         // C*3  (= GEMM K)
#define ALPHA 0.2f
#define EPS 1e-5f

// GEMM tiling (HMMA + ldmatrix path)
#define BK 64                       // bf16 K per stage
#define TILEB 16384                 // 128 rows x 64 bf16 x 2B (128B rows, xor-swizzled)
#define STAGEB 65536                // Ahi, Alo, Bhi, Blo tiles
#define NSTAGE 3
#define NIT (KTOT / BK)             // 192
#define SMEM_DYN (NSTAGE * STAGEB)  // 196608

// ---------------- device scratch (no allocations allowed) -------------------
__device__ float         g_Wh[COLS * NN * HH];
__device__ float         g_f1[COLS * NN];
__device__ float         g_f2[COLS * NN];
__device__ unsigned      g_mask[NN * 8];
__device__ float         g_S[(size_t)COLS * CC];        // spatial [col][c]
__device__ __nv_bfloat16 g_Bhi[(size_t)COLS * KTOT];
__device__ __nv_bfloat16 g_Blo[(size_t)COLS * KTOT];
__device__ float         g_Yt[(size_t)COLS * CC];       // conv out [col][o]

// ---------------- PTX helpers ----------------------------------------------
__device__ __forceinline__ void cp16(unsigned dst, const void* src) {
    asm volatile("cp.async.cg.shared.global [%0], [%1], 16;" :: "r"(dst), "l"(src) : "memory");
}
__device__ __forceinline__ void cp_commit() {
    asm volatile("cp.async.commit_group;" ::: "memory");
}
__device__ __forceinline__ void ldsm4(unsigned* r, unsigned addr) {
    asm volatile("ldmatrix.sync.aligned.m8n8.x4.shared.b16 {%0,%1,%2,%3}, [%4];"
                 : "=r"(r[0]), "=r"(r[1]), "=r"(r[2]), "=r"(r[3]) : "r"(addr));
}
__device__ __forceinline__ void sts64(unsigned addr, unsigned v0, unsigned v1) {
    asm volatile("st.shared.v2.b32 [%0], {%1,%2};" :: "r"(addr), "r"(v0), "r"(v1) : "memory");
}
__device__ __forceinline__ void mma16816(float* d, const unsigned* a, const unsigned* b) {
    asm volatile(
        "mma.sync.aligned.m16n8k16.row.col.f32.bf16.bf16.f32 "
        "{%0,%1,%2,%3}, {%4,%5,%6,%7}, {%8,%9}, {%0,%1,%2,%3};"
        : "+f"(d[0]), "+f"(d[1]), "+f"(d[2]), "+f"(d[3])
        : "r"(a[0]), "r"(a[1]), "r"(a[2]), "r"(a[3]), "r"(b[0]), "r"(b[1]));
}
__device__ __forceinline__ unsigned pack2bf16(float x, float y) {
    __nv_bfloat162 v = __floats2bfloat162_rn(x, y);
    return *reinterpret_cast<unsigned*>(&v);
}

// ---------------------------------------------------------------------------
// Kernel 0: adjacency bitmask
// ---------------------------------------------------------------------------
__global__ void k_mask(const float* __restrict__ adj) {
    int idx = blockIdx.x * blockDim.x + threadIdx.x;
    if (idx >= NN * 8) return;
    int i = idx >> 3, w = idx & 7;
    unsigned m = 0;
#pragma unroll
    for (int b = 0; b < 32; b++)
        if (adj[i * NN + w * 32 + b] > 0.0f) m |= (1u << b);
    g_mask[idx] = m;
}

// ---------------------------------------------------------------------------
// Kernel 1: Wh = x @ W ; f1 = Wh.a1 ; f2 = Wh.a2
// ---------------------------------------------------------------------------
__global__ void k_wh(const float* __restrict__ x, const float* __restrict__ W,
                     const float* __restrict__ a1, const float* __restrict__ a2) {
    __shared__ float sW[FF * HH];
    __shared__ float sa1[HH], sa2[HH];
    int t = threadIdx.x;
    sW[t] = W[t];
    if (t < HH) { sa1[t] = a1[t]; sa2[t] = a2[t]; }
    __syncthreads();

    int bs = blockIdx.x;
    const float* xr = x + (size_t)(bs * NN + t) * FF;
    float xv[FF];
#pragma unroll
    for (int f = 0; f < FF; f += 4) {
        float4 v = *(const float4*)(xr + f);
        xv[f] = v.x; xv[f + 1] = v.y; xv[f + 2] = v.z; xv[f + 3] = v.w;
    }
    float wh[HH];
#pragma unroll
    for (int h = 0; h < HH; h++) wh[h] = 0.0f;
#pragma unroll
    for (int f = 0; f < FF; f++)
#pragma unroll
        for (int h = 0; h < HH; h++) wh[h] += xv[f] * sW[f * HH + h];

    float f1 = 0.0f, f2 = 0.0f;
#pragma unroll
    for (int h = 0; h < HH; h++) { f1 += wh[h] * sa1[h]; f2 += wh[h] * sa2[h]; }

    float* whr = g_Wh + (size_t)(bs * NN + t) * HH;
#pragma unroll
    for (int h = 0; h < HH; h += 4)
        *(float4*)(whr + h) = make_float4(wh[h], wh[h + 1], wh[h + 2], wh[h + 3]);
    g_f1[bs * NN + t] = f1;
    g_f2[bs * NN + t] = f2;
}

// ---------------------------------------------------------------------------
// Kernel 2: attention softmax + spatial = attn @ Wh -> g_S[col][c]
// ---------------------------------------------------------------------------
__global__ void k_attn() {
    __shared__ float    sWh[NN * HH];
    __shared__ float    sf2[NN];
    __shared__ unsigned smask[NN * 8];

    int bs = blockIdx.x;
    int t = threadIdx.x;

    for (int idx = t; idx < NN * HH; idx += 256) sWh[idx] = g_Wh[(size_t)bs * NN * HH + idx];
    sf2[t] = g_f2[bs * NN + t];
    for (int idx = t; idx < NN * 8; idx += 256) smask[idx] = g_mask[idx];
    __syncthreads();

    float f1i = g_f1[bs * NN + t];

    float m = -1e30f;
#pragma unroll 1
    for (int jw = 0; jw < 8; jw++) {
        unsigned wd = smask[t * 8 + jw];
#pragma unroll
        for (int bit = 0; bit < 32; bit++) {
            float e = f1i + sf2[jw * 32 + bit];
            e = e > 0.0f ? e : ALPHA * e;
            if ((wd >> bit) & 1u) m = fmaxf(m, e);
        }
    }

    float sum = 0.0f;
    float acc[HH];
#pragma unroll
    for (int h = 0; h < HH; h++) acc[h] = 0.0f;

#pragma unroll 1
    for (int jw = 0; jw < 8; jw++) {
        unsigned wd = smask[t * 8 + jw];
#pragma unroll
        for (int bit = 0; bit < 32; bit++) {
            int j = jw * 32 + bit;
            float e = f1i + sf2[j];
            e = e > 0.0f ? e : ALPHA * e;
            float w = ((wd >> bit) & 1u) ? __expf(e - m) : 0.0f;
            sum += w;
#pragma unroll
            for (int h = 0; h < HH; h++) acc[h] += w * sWh[j * HH + h];
        }
    }

    float inv = 1.0f / sum;
    float* so = g_S + (size_t)bs * CC + t * HH;
#pragma unroll
    for (int h = 0; h < HH; h += 4)
        *(float4*)(so + h) = make_float4(acc[h] * inv, acc[h + 1] * inv,
                                         acc[h + 2] * inv, acc[h + 3] * inv);
}

// ---------------------------------------------------------------------------
// Kernel 3: build B (K-major, [col][c*3+tap]) in split bf16 from g_S.
// ---------------------------------------------------------------------------
__global__ void k_buildB() {
    int col = blockIdx.x;           // 0..511
    int s = col & 63;
    for (int c = threadIdx.x; c < CC; c += 256) {
        float vm = (s > 0)  ? g_S[(size_t)(col - 1) * CC + c] : 0.0f;
        float v0 =            g_S[(size_t)col * CC + c];
        float vp = (s < 63) ? g_S[(size_t)(col + 1) * CC + c] : 0.0f;
        float t3[3] = {vm, v0, vp};
        size_t base = (size_t)col * KTOT + 3 * (size_t)c;
#pragma unroll
        for (int tap = 0; tap < 3; tap++) {
            __nv_bfloat16 h = __float2bfloat16(t3[tap]);
            __nv_bfloat16 l = __float2bfloat16(t3[tap] - __bfloat162float(h));
            g_Bhi[base + tap] = h;
            g_Blo[base + tap] = l;
        }
    }
}

// ---------------------------------------------------------------------------
// Kernel 4: HMMA 3xBF16 GEMM, fp32 weights split in-kernel.
// 128x128 CTA tile, BK=64, 3 stages, 8 warps (4M x 2N), warp tile m32n64.
// Smem tiles: 128 rows x 128B, xor-swizzled; ldmatrix.x4 fragment loads.
// ---------------------------------------------------------------------------
__global__ __launch_bounds__(256, 1) void k_conv_mma(const float* __restrict__ wsrc) {
    extern __shared__ __align__(1024) char smem[];
    unsigned sb0 = (unsigned)__cvta_generic_to_shared(smem);

    int t = threadIdx.x;
    int wid = t >> 5;
    int L = t & 31;
    int wm = wid & 3;          // 4 warps along M (o)
    int wn = wid >> 2;         // 2 warps along N (col)
    int colBase = blockIdx.x * 128;
    int oBase = blockIdx.y * 128;

    // ---- loader indexing ----
    int ar = t >> 1;           // A row (0..127), 2 threads per row
    int ah2 = t & 1;           // interleaved 16B-chunk selector within row
    const float* aG = wsrc + (size_t)(oBase + ar) * KTOT;
    unsigned aRowB = (unsigned)(ar * 128);
    unsigned aSwz = (unsigned)((ar & 7) << 4);

    int bc = t >> 1;           // B col (0..127)
    int bh2 = t & 1;
    const __nv_bfloat16* bHg = g_Bhi + (size_t)(colBase + bc) * KTOT;
    const __nv_bfloat16* bLg = g_Blo + (size_t)(colBase + bc) * KTOT;
    unsigned bRowB = (unsigned)(bc * 128);
    unsigned bSwz = (unsigned)((bc & 7) << 4);

    // ---- fragment (ldmatrix) indexing ----
    int l16 = L & 15;
    unsigned chB = (unsigned)(L >> 4);          // k-half selector
    unsigned fSwz = (unsigned)((l16 & 7) << 4); // row%8 xor bits (tiles are 16-row aligned)
    unsigned aRow[2], bRow[4];
#pragma unroll
    for (int mt = 0; mt < 2; mt++) aRow[mt] = (unsigned)((wm * 32 + mt * 16 + l16) * 128);
#pragma unroll
    for (int q = 0; q < 4; q++) bRow[q] = (unsigned)((wn * 64 + q * 16 + l16) * 128);

    float d[2][8][4];
#pragma unroll
    for (int mt = 0; mt < 2; mt++)
#pragma unroll
        for (int nt = 0; nt < 8; nt++)
#pragma unroll
            for (int qq = 0; qq < 4; qq++) d[mt][nt][qq] = 0.0f;

    // ---- prologue: stages 0 and 1 ----
#pragma unroll
    for (int st = 0; st < 2; st++) {
        unsigned sbs = sb0 + (unsigned)st * STAGEB;
        int kb = st * BK;
        // B via cp.async
#pragma unroll
        for (int j = 0; j < 4; j++) {
            unsigned ch = (unsigned)((j * 2 + bh2) * 16);
            unsigned dsw = bRowB + (ch ^ bSwz);
            cp16(sbs + 32768 + dsw, bHg + kb + (j * 2 + bh2) * 8);
            cp16(sbs + 49152 + dsw, bLg + kb + (j * 2 + bh2) * 8);
        }
        cp_commit();
        // A: LDG fp32 -> split -> STS
        float4 av[8];
#pragma unroll
        for (int j = 0; j < 8; j++)
            av[j] = *(const float4*)(aG + kb + j * 8 + ah2 * 4);
#pragma unroll
        for (int j = 0; j < 8; j++) {
            float xs[4] = {av[j].x, av[j].y, av[j].z, av[j].w};
            float hs[4], ls[4];
#pragma unroll
            for (int q = 0; q < 4; q++) {
                hs[q] = __bfloat162float(__float2bfloat16(xs[q]));
                ls[q] = xs[q] - hs[q];
            }
            unsigned h01 = pack2bf16(hs[0], hs[1]), h23 = pack2bf16(hs[2], hs[3]);
            unsigned l01 = pack2bf16(ls[0], ls[1]), l23 = pack2bf16(ls[2], ls[3]);
            unsigned dsw = aRowB + (((unsigned)(j * 16)) ^ aSwz) + ah2 * 8;
            sts64(sbs + dsw, h01, h23);
            sts64(sbs + 16384 + dsw, l01, l23);
        }
    }

    // ---- main loop ----
    for (int kt = 0; kt < NIT; kt++) {
        asm volatile("cp.async.wait_group 1;" ::: "memory");
        __syncthreads();

        float4 av[8];
        bool has = (kt + 2) < NIT;
        if (has) {
            unsigned sbs = sb0 + (unsigned)((kt + 2) % 3) * STAGEB;
            int kb = (kt + 2) * BK;
#pragma unroll
            for (int j = 0; j < 4; j++) {
                unsigned ch = (unsigned)((j * 2 + bh2) * 16);
                unsigned dsw = bRowB + (ch ^ bSwz);
                cp16(sbs + 32768 + dsw, bHg + kb + (j * 2 + bh2) * 8);
                cp16(sbs + 49152 + dsw, bLg + kb + (j * 2 + bh2) * 8);
            }
            cp_commit();
#pragma unroll
            for (int j = 0; j < 8; j++)
                av[j] = *(const float4*)(aG + kb + j * 8 + ah2 * 4);
        } else {
            cp_commit();
        }

        unsigned sb = sb0 + (unsigned)(kt % 3) * STAGEB;

#pragma unroll
        for (int ks = 0; ks < 4; ks++) {
            unsigned ch = ((unsigned)(ks * 2) + chB) << 4;
            unsigned chx = ch ^ fSwz;
            unsigned ahf[2][4], alf[2][4], bhf[4][4], blf[4][4];
#pragma unroll
            for (int mt = 0; mt < 2; mt++) {
                ldsm4(ahf[mt], sb + aRow[mt] + chx);
                ldsm4(alf[mt], sb + 16384 + aRow[mt] + chx);
            }
#pragma unroll
            for (int q = 0; q < 4; q++) {
                ldsm4(bhf[q], sb + 32768 + bRow[q] + chx);
                ldsm4(blf[q], sb + 49152 + bRow[q] + chx);
            }
#pragma unroll
            for (int mt = 0; mt < 2; mt++)
#pragma unroll
                for (int q = 0; q < 4; q++)
#pragma unroll
                    for (int h = 0; h < 2; h++) {
                        unsigned bhv[2] = {bhf[q][h], bhf[q][h + 2]};
                        unsigned blv[2] = {blf[q][h], blf[q][h + 2]};
                        float* dd = d[mt][q * 2 + h];
                        mma16816(dd, ahf[mt], bhv);
                        mma16816(dd, alf[mt], bhv);
                        mma16816(dd, ahf[mt], blv);
                    }
        }

        if (has) {
            unsigned sbs = sb0 + (unsigned)((kt + 2) % 3) * STAGEB;
#pragma unroll
            for (int j = 0; j < 8; j++) {
                float xs[4] = {av[j].x, av[j].y, av[j].z, av[j].w};
                float hs[4], ls[4];
#pragma unroll
                for (int q = 0; q < 4; q++) {
                    hs[q] = __bfloat162float(__float2bfloat16(xs[q]));
                    ls[q] = xs[q] - hs[q];
                }
                unsigned h01 = pack2bf16(hs[0], hs[1]), h23 = pack2bf16(hs[2], hs[3]);
                unsigned l01 = pack2bf16(ls[0], ls[1]), l23 = pack2bf16(ls[2], ls[3]);
                unsigned dsw = aRowB + (((unsigned)(j * 16)) ^ aSwz) + ah2 * 8;
                sts64(sbs + dsw, h01, h23);
                sts64(sbs + 16384 + dsw, l01, l23);
            }
        }
    }

    // ---- epilogue: Yt[col][o] ----
    int gid = L >> 2, tid4 = L & 3;
#pragma unroll
    for (int mt = 0; mt < 2; mt++) {
        int r = oBase + wm * 32 + mt * 16 + gid;
#pragma unroll
        for (int nt = 0; nt < 8; nt++) {
            int c = colBase + wn * 64 + nt * 8 + tid4 * 2;
            g_Yt[(size_t)c * CC + r]           = d[mt][nt][0];
            g_Yt[(size_t)(c + 1) * CC + r]     = d[mt][nt][1];
            g_Yt[(size_t)c * CC + r + 8]       = d[mt][nt][2];
            g_Yt[(size_t)(c + 1) * CC + r + 8] = d[mt][nt][3];
        }
    }
}

// ---------------------------------------------------------------------------
// Kernel 5: bias + BN + ReLU + residual + LayerNorm(H=16)
// ---------------------------------------------------------------------------
__global__ void k_final(const float* __restrict__ x,
                        const float* __restrict__ conv_b,
                        const float* __restrict__ bn_g, const float* __restrict__ bn_b,
                        const float* __restrict__ bn_m, const float* __restrict__ bn_v,
                        const float* __restrict__ ln_g, const float* __restrict__ ln_b,
                        float* __restrict__ out) {
    int bs = blockIdx.x, n = threadIdx.x;
    size_t base = (size_t)bs * CC + n * HH;
    size_t obase = (size_t)n * HH;

    float v[HH];
#pragma unroll
    for (int h = 0; h < HH; h += 4) {
        float4 y = *(const float4*)&g_Yt[base + h];
        float4 cb = *(const float4*)&conv_b[obase + h];
        float4 bm = *(const float4*)&bn_m[obase + h];
        float4 bvr = *(const float4*)&bn_v[obase + h];
        float4 bg = *(const float4*)&bn_g[obase + h];
        float4 bb = *(const float4*)&bn_b[obase + h];
        float4 xr = *(const float4*)&x[base + h];
        float yy[4] = {y.x, y.y, y.z, y.w};
        float cbv[4] = {cb.x, cb.y, cb.z, cb.w};
        float bmv[4] = {bm.x, bm.y, bm.z, bm.w};
        float bvv[4] = {bvr.x, bvr.y, bvr.z, bvr.w};
        float bgv[4] = {bg.x, bg.y, bg.z, bg.w};
        float bbv[4] = {bb.x, bb.y, bb.z, bb.w};
        float xv[4] = {xr.x, xr.y, xr.z, xr.w};
#pragma unroll
        for (int q = 0; q < 4; q++) {
            float val = yy[q] + cbv[q];
            val = (val - bmv[q]) * rsqrtf(bvv[q] + EPS) * bgv[q] + bbv[q];
            val = fmaxf(val, 0.0f);
            v[h + q] = val + xv[q];
        }
    }

    float mu = 0.0f;
#pragma unroll
    for (int h = 0; h < HH; h++) mu += v[h];
    mu *= (1.0f / HH);
    float var = 0.0f;
#pragma unroll
    for (int h = 0; h < HH; h++) { float dd = v[h] - mu; var += dd * dd; }
    var *= (1.0f / HH);
    float is = rsqrtf(var + EPS);

#pragma unroll
    for (int h = 0; h < HH; h++)
        out[base + h] = (v[h] - mu) * is * ln_g[h] + ln_b[h];
}

// ---------------------------------------------------------------------------
extern "C" void kernel_launch(void* const* d_in, const int* in_sizes, int n_in,
                              void* d_out, int out_size) {
    const float* x      = (const float*)d_in[0];
    const float* adj    = (const float*)d_in[1];
    const float* W      = (const float*)d_in[2];
    const float* a1     = (const float*)d_in[3];
    const float* a2     = (const float*)d_in[4];
    const float* conv_w = (const float*)d_in[5];
    const float* conv_b = (const float*)d_in[6];
    const float* bn_g   = (const float*)d_in[7];
    const float* bn_b   = (const float*)d_in[8];
    const float* bn_m   = (const float*)d_in[9];
    const float* bn_v   = (const float*)d_in[10];
    const float* ln_g   = (const float*)d_in[11];
    const float* ln_b   = (const float*)d_in[12];
    float* out = (float*)d_out;

    cudaFuncSetAttribute(k_conv_mma, cudaFuncAttributeMaxDynamicSharedMemorySize, SMEM_DYN);

    k_mask<<<8, 256>>>(adj);
    k_wh<<<512, 256>>>(x, W, a1, a2);
    k_attn<<<512, 256>>>();
    k_buildB<<<512, 256>>>();
    k_conv_mma<<<dim3(4, 32), 256, SMEM_DYN>>>(conv_w);
    k_final<<<512, 256>>>(x, conv_b, bn_g, bn_b, bn_m, bn_v, ln_g, ln_b, out);
}